// round 15
// baseline (speedup 1.0000x reference)
#include <cuda_runtime.h>
#include <cuda_fp16.h>

#define BB 128
#define LL 512
#define KN 8
#define DD 300
#define CC 14
#define LCHUNK 64
#define NCHUNK (LL / LCHUNK)   // 8
#define NROWS 4905             // NUM_NODES + 1
#define RSTRIDE 320            // halves per row: 640B = 5 x 128B sectors
#define RH2 (RSTRIDE / 2)      // 160 half2 per row
#define CVT_WARPS 16
#define CVT_BLKS ((NROWS + CVT_WARPS - 1) / CVT_WARPS)   // 307
#define STAGES 4
#define SPOS (LCHUNK / STAGES)   // 16 positions per stage
#define SENT (SPOS * KN)         // 128 metadata entries per stage

__device__ __half2 g_Rh2[NROWS * RH2];
__device__ float g_part[NCHUNK * BB * DD];

__device__ __forceinline__ void pdl_wait()
{
    asm volatile("griddepcontrol.wait;" ::: "memory");
}

// ---- convert: R -> fp16 padded rows (normal launch) ----
__global__ __launch_bounds__(512)
void convert_kernel(const float* __restrict__ R)
{
    const int wid  = threadIdx.x >> 5;
    const int lane = threadIdx.x & 31;
    const int row  = blockIdx.x * CVT_WARPS + wid;
    if (row >= NROWS) return;

    const float* src = R + row * DD;
    __half2*     dst = g_Rh2 + row * RH2;

    float2 v[5];
    #pragma unroll
    for (int j = 0; j < 5; ++j) {
        const int tt = lane + j * 32;
        v[j] = (tt < DD / 2) ? *(const float2*)&src[tt * 2]
                             : make_float2(0.f, 0.f);
    }
    #pragma unroll
    for (int j = 0; j < 5; ++j) {
        const int tt = lane + j * 32;
        if (tt < RH2)
            dst[tt] = __floats2half2_rn(v[j].x, v[j].y);
    }
}

// ---- pool: 4-stage software pipeline; metadata gathers hide under mainloop ----
__global__ __launch_bounds__(160)
void gnn_pool_kernel(const int*   __restrict__ master,
                     const int*   __restrict__ slave,
                     const int*   __restrict__ edge,
                     const float* __restrict__ E,
                     const float* __restrict__ Ngate)
{
    const int b     = blockIdx.y;
    const int chunk = blockIdx.x;
    const int tid   = threadIdx.x;

    __shared__ __align__(16) int   s_node[STAGES][SENT];
    __shared__ __align__(16) float s_e[STAGES][SENT];
    __shared__ int   s_m[STAGES][SPOS];
    __shared__ float s_g[STAGES][SPOS];

    const int base = b * LL + chunk * LCHUNK;

    // Prefetch registers (live across a mainloop stage)
    int   pf_n = 0;  float pf_e = 0.f;
    int   pf_m = 0;  float pf_g = 0.f;

    // Issue gather LDGs for stage s into registers (in-order issue => these
    // are in flight while the previous mainloop stage executes).
    auto prefetch = [&](int s) {
        const int sb = base + s * SPOS;
        if (tid < SENT) {
            const int pos = sb + (tid >> 3);
            const int k   = tid & 7;
            pf_n = slave[pos * KN + k] * RH2;
            pf_e = E[edge[pos * KN + k]];
        } else if (tid < SENT + SPOS) {
            const int m = master[sb + (tid - SENT)];
            pf_m = m * RH2;
            pf_g = Ngate[m];
        }
    };

    // Commit prefetched registers to stage-s smem (stalls on gather completion,
    // which by then has been hidden behind the previous mainloop stage).
    auto commit = [&](int s) {
        if (tid < SENT) {
            s_node[s][tid] = pf_n;
            s_e[s][tid]    = pf_e;
        } else if (tid < SENT + SPOS) {
            s_m[s][tid - SENT] = pf_m;
            s_g[s][tid - SENT] = pf_g;
        }
        __syncthreads();
    };

    const bool active = (tid < 150);   // 150 half2 lanes cover 300 dims
    const __half2* Rbase = g_Rh2 + tid;
    float2 acc = make_float2(0.f, 0.f);

    // Mainloop over one stage's 16 positions
    auto mainstage = [&](int s) {
        if (!active) return;
        #pragma unroll 4
        for (int li = 0; li < SPOS; ++li) {
            const int4   n0 = *(const int4*)  &s_node[s][li * KN];
            const int4   n1 = *(const int4*)  &s_node[s][li * KN + 4];
            const float4 e0 = *(const float4*)&s_e[s][li * KN];
            const float4 e1 = *(const float4*)&s_e[s][li * KN + 4];

            const float2 f0 = __half22float2(Rbase[n0.x]);
            const float2 f1 = __half22float2(Rbase[n0.y]);
            const float2 f2 = __half22float2(Rbase[n0.z]);
            const float2 f3 = __half22float2(Rbase[n0.w]);
            const float2 f4 = __half22float2(Rbase[n1.x]);
            const float2 f5 = __half22float2(Rbase[n1.y]);
            const float2 f6 = __half22float2(Rbase[n1.z]);
            const float2 f7 = __half22float2(Rbase[n1.w]);
            const float2 fm = __half22float2(Rbase[s_m[s][li]]);

            float mx0 = f0.x * e0.x;
            float mx1 = f0.y * e0.x;
            mx0 = fmaxf(mx0, f1.x * e0.y);  mx1 = fmaxf(mx1, f1.y * e0.y);
            mx0 = fmaxf(mx0, f2.x * e0.z);  mx1 = fmaxf(mx1, f2.y * e0.z);
            mx0 = fmaxf(mx0, f3.x * e0.w);  mx1 = fmaxf(mx1, f3.y * e0.w);
            mx0 = fmaxf(mx0, f4.x * e1.x);  mx1 = fmaxf(mx1, f4.y * e1.x);
            mx0 = fmaxf(mx0, f5.x * e1.y);  mx1 = fmaxf(mx1, f5.y * e1.y);
            mx0 = fmaxf(mx0, f6.x * e1.z);  mx1 = fmaxf(mx1, f6.y * e1.z);
            mx0 = fmaxf(mx0, f7.x * e1.w);  mx1 = fmaxf(mx1, f7.y * e1.w);

            const float g = s_g[s][li];
            acc.x += mx0 + g * (fm.x - mx0);
            acc.y += mx1 + g * (fm.y - mx1);
        }
    };

    // ---- pipeline ----
    prefetch(0);          // pre-wait: depends only on raw inputs
    pdl_wait();           // g_Rh2 ready (convert complete)
    commit(0);
    prefetch(1);
    mainstage(0);         // hides stage-1 gathers
    commit(1);
    prefetch(2);
    mainstage(1);         // hides stage-2 gathers
    commit(2);
    prefetch(3);
    mainstage(2);         // hides stage-3 gathers
    commit(3);
    mainstage(3);

    if (active) {
        float2* outp = (float2*)&g_part[(chunk * BB + b) * DD];
        outp[tid] = acc;
    }
}

__global__ __launch_bounds__(448)
void head_kernel(const float* __restrict__ W,
                 const float* __restrict__ bias,
                 float* __restrict__ out)
{
    const int b    = blockIdx.x;
    const int tid  = threadIdx.x;
    const int wid  = tid >> 5;
    const int lane = tid & 31;

    __shared__ float sx[DD];
    __shared__ float sh[CC];

    // PRE-WAIT: W + bias loads (independent of pool)
    float wreg[10];
    float bb = 0.f;
    if (wid < CC) {
        #pragma unroll
        for (int it = 0; it < 10; ++it) {
            const int d = lane + it * 32;
            wreg[it] = (d < DD) ? W[wid * DD + d] : 0.f;
        }
        bb = bias[wid];
    }

    pdl_wait();   // g_part complete

    if (tid < 150) {
        float2 s = make_float2(0.f, 0.f);
        #pragma unroll
        for (int c = 0; c < NCHUNK; ++c) {
            const float2 p = *(const float2*)&g_part[(c * BB + b) * DD + tid * 2];
            s.x += p.x;
            s.y += p.y;
        }
        sx[tid * 2]     = s.x;
        sx[tid * 2 + 1] = s.y;
    }
    __syncthreads();

    if (wid < CC) {
        float s = 0.f;
        #pragma unroll
        for (int it = 0; it < 10; ++it) {
            const int d = lane + it * 32;
            if (d < DD) s += sx[d] * wreg[it];
        }
        #pragma unroll
        for (int off = 16; off; off >>= 1)
            s += __shfl_down_sync(0xffffffffu, s, off);
        if (lane == 0)
            sh[wid] = fmaxf(s + bb, 0.f);
    }
    __syncthreads();

    if (wid == 0) {
        const float h = (lane < CC) ? sh[lane] : -1e30f;
        float m = h;
        #pragma unroll
        for (int off = 16; off; off >>= 1)
            m = fmaxf(m, __shfl_xor_sync(0xffffffffu, m, off));
        const float e = (lane < CC) ? expf(h - m) : 0.f;
        float sum = e;
        #pragma unroll
        for (int off = 16; off; off >>= 1)
            sum += __shfl_xor_sync(0xffffffffu, sum, off);
        if (lane < CC)
            out[b * CC + lane] = e / sum;
    }
}

extern "C" void kernel_launch(void* const* d_in, const int* in_sizes, int n_in,
                              void* d_out, int out_size)
{
    const int*   master = (const int*)  d_in[0];
    const int*   slave  = (const int*)  d_in[1];
    const int*   edge   = (const int*)  d_in[2];
    const float* R      = (const float*)d_in[3];
    const float* E      = (const float*)d_in[4];
    const float* Ngate  = (const float*)d_in[5];
    const float* W      = (const float*)d_in[6];
    const float* bias   = (const float*)d_in[7];
    float* out = (float*)d_out;

    cudaLaunchAttribute attr[1];
    attr[0].id = cudaLaunchAttributeProgrammaticStreamSerialization;
    attr[0].val.programmaticStreamSerializationAllowed = 1;

    // 1) convert: normal launch
    convert_kernel<<<CVT_BLKS, 512>>>(R);

    // 2) pool: PDL — pipelined metadata gathers hide under the mainloop
    {
        cudaLaunchConfig_t cfg = {};
        cfg.gridDim  = dim3(NCHUNK, BB);
        cfg.blockDim = dim3(160);
        cfg.stream   = 0;
        cfg.attrs    = attr;
        cfg.numAttrs = 1;
        cudaLaunchKernelEx(&cfg, gnn_pool_kernel, master, slave, edge, E, Ngate);
    }

    // 3) head: PDL — W preload overlaps pool drain
    {
        cudaLaunchConfig_t cfg = {};
        cfg.gridDim  = dim3(BB);
        cfg.blockDim = dim3(448);
        cfg.stream   = 0;
        cfg.attrs    = attr;
        cfg.numAttrs = 1;
        cudaLaunchKernelEx(&cfg, head_kernel, W, bias, out);
    }
}

// round 16
// speedup vs baseline: 1.1273x; 1.1273x over previous
#include <cuda_runtime.h>
#include <cuda_fp16.h>

#define BB 128
#define LL 512
#define KN 8
#define DD 300
#define CC 14
#define LCHUNK 64
#define NCHUNK (LL / LCHUNK)   // 8
#define NPOS (BB * LL)         // 65536 positions
#define NROWS 4905             // NUM_NODES + 1
#define RSTRIDE 320            // halves per row: 640B = 5 x 128B sectors
#define RH2 (RSTRIDE / 2)      // 160 half2 per row
#define CVT_WARPS 16
#define CVT_BLKS ((NROWS + CVT_WARPS - 1) / CVT_WARPS)   // 307
#define EGATH_BLKS 256          // E gathers: 256 blks x 512 thr x 4
#define NGATH_BLKS 32           // Ngate gathers: 32 blks x 512 thr x 4

__device__ __half2 g_Rh2[NROWS * RH2];
__device__ float g_part[NCHUNK * BB * DD];
__device__ __align__(16) float g_e[NPOS * KN];   // E[edge]
__device__ __align__(16) float g_g[NPOS];        // Ngate[master]

__device__ __forceinline__ void pdl_wait()
{
    asm volatile("griddepcontrol.wait;" ::: "memory");
}

// ---- prep: ONLY the true gathers + fp16 convert (no index copies) ----
__global__ __launch_bounds__(512)
void prep_kernel(const float* __restrict__ R,
                 const int*   __restrict__ master,
                 const int*   __restrict__ edge,
                 const float* __restrict__ E,
                 const float* __restrict__ Ngate)
{
    const int t = threadIdx.x;

    if (blockIdx.x < CVT_BLKS) {
        // ---- convert role: one warp per R row, MLP=5 ----
        const int wid  = t >> 5;
        const int lane = t & 31;
        const int row  = blockIdx.x * CVT_WARPS + wid;
        if (row >= NROWS) return;

        const float* src = R + row * DD;
        __half2*     dst = g_Rh2 + row * RH2;

        float2 v[5];
        #pragma unroll
        for (int j = 0; j < 5; ++j) {
            const int tt = lane + j * 32;
            v[j] = (tt < DD / 2) ? *(const float2*)&src[tt * 2]
                                 : make_float2(0.f, 0.f);
        }
        #pragma unroll
        for (int j = 0; j < 5; ++j) {
            const int tt = lane + j * 32;
            if (tt < RH2)
                dst[tt] = __floats2half2_rn(v[j].x, v[j].y);
        }
    } else if (blockIdx.x < CVT_BLKS + EGATH_BLKS) {
        // ---- E gathers: int4 edge load -> 4 independent gathers ----
        const int gid = (blockIdx.x - CVT_BLKS) * 512 + t;   // 0..131071
        const int4 e4 = ((const int4*)edge)[gid];

        const float v0 = E[e4.x];
        const float v1 = E[e4.y];
        const float v2 = E[e4.z];
        const float v3 = E[e4.w];

        ((float4*)g_e)[gid] = make_float4(v0, v1, v2, v3);
    } else {
        // ---- Ngate gathers ----
        const int gid = (blockIdx.x - CVT_BLKS - EGATH_BLKS) * 512 + t;  // 0..16383
        const int4 m4 = ((const int4*)master)[gid];

        const float g0 = Ngate[m4.x];
        const float g1 = Ngate[m4.y];
        const float g2 = Ngate[m4.z];
        const float g3 = Ngate[m4.w];

        ((float4*)g_g)[gid] = make_float4(g0, g1, g2, g3);
    }
}

__global__ __launch_bounds__(160)
void gnn_pool_kernel(const int* __restrict__ master,
                     const int* __restrict__ slave)
{
    const int b     = blockIdx.y;
    const int chunk = blockIdx.x;
    const int tid   = threadIdx.x;

    pdl_wait();   // prep outputs (g_Rh2, g_e, g_g) complete

    __shared__ __align__(16) int   s_node[LCHUNK * KN];
    __shared__ __align__(16) float s_e[LCHUNK * KN];
    __shared__ int   s_m[LCHUNK];
    __shared__ float s_g[LCHUNK];

    const int base = b * LL + chunk * LCHUNK;

    // Prologue: slave/master read directly (L2-hot from prep) + scale here.
    for (int i = tid; i < LCHUNK * KN; i += 160) {
        s_node[i] = slave[base * KN + i] * RH2;
        s_e[i]    = g_e[base * KN + i];
    }
    if (tid < LCHUNK) {
        s_m[tid] = master[base + tid] * RH2;
        s_g[tid] = g_g[base + tid];
    }
    __syncthreads();

    if (tid >= 150) return;   // 150 half2 lanes cover 300 dims

    const __half2* Rbase = g_Rh2 + tid;
    float2 acc = make_float2(0.f, 0.f);

    #pragma unroll 4
    for (int li = 0; li < LCHUNK; ++li) {
        const int4   n0 = *(const int4*)  &s_node[li * KN];
        const int4   n1 = *(const int4*)  &s_node[li * KN + 4];
        const float4 e0 = *(const float4*)&s_e[li * KN];
        const float4 e1 = *(const float4*)&s_e[li * KN + 4];

        const float2 f0 = __half22float2(Rbase[n0.x]);
        const float2 f1 = __half22float2(Rbase[n0.y]);
        const float2 f2 = __half22float2(Rbase[n0.z]);
        const float2 f3 = __half22float2(Rbase[n0.w]);
        const float2 f4 = __half22float2(Rbase[n1.x]);
        const float2 f5 = __half22float2(Rbase[n1.y]);
        const float2 f6 = __half22float2(Rbase[n1.z]);
        const float2 f7 = __half22float2(Rbase[n1.w]);
        const float2 fm = __half22float2(Rbase[s_m[li]]);

        float mx0 = f0.x * e0.x;
        float mx1 = f0.y * e0.x;
        mx0 = fmaxf(mx0, f1.x * e0.y);  mx1 = fmaxf(mx1, f1.y * e0.y);
        mx0 = fmaxf(mx0, f2.x * e0.z);  mx1 = fmaxf(mx1, f2.y * e0.z);
        mx0 = fmaxf(mx0, f3.x * e0.w);  mx1 = fmaxf(mx1, f3.y * e0.w);
        mx0 = fmaxf(mx0, f4.x * e1.x);  mx1 = fmaxf(mx1, f4.y * e1.x);
        mx0 = fmaxf(mx0, f5.x * e1.y);  mx1 = fmaxf(mx1, f5.y * e1.y);
        mx0 = fmaxf(mx0, f6.x * e1.z);  mx1 = fmaxf(mx1, f6.y * e1.z);
        mx0 = fmaxf(mx0, f7.x * e1.w);  mx1 = fmaxf(mx1, f7.y * e1.w);

        const float g = s_g[li];
        acc.x += mx0 + g * (fm.x - mx0);
        acc.y += mx1 + g * (fm.y - mx1);
    }

    float2* outp = (float2*)&g_part[(chunk * BB + b) * DD];
    outp[tid] = acc;
}

__global__ __launch_bounds__(448)
void head_kernel(const float* __restrict__ W,
                 const float* __restrict__ bias,
                 float* __restrict__ out)
{
    const int b    = blockIdx.x;
    const int tid  = threadIdx.x;
    const int wid  = tid >> 5;
    const int lane = tid & 31;

    __shared__ float sx[DD];
    __shared__ float sh[CC];

    // PRE-WAIT: W + bias loads (independent of pool)
    float wreg[10];
    float bb = 0.f;
    if (wid < CC) {
        #pragma unroll
        for (int it = 0; it < 10; ++it) {
            const int d = lane + it * 32;
            wreg[it] = (d < DD) ? W[wid * DD + d] : 0.f;
        }
        bb = bias[wid];
    }

    pdl_wait();   // g_part complete

    if (tid < 150) {
        float2 s = make_float2(0.f, 0.f);
        #pragma unroll
        for (int c = 0; c < NCHUNK; ++c) {
            const float2 p = *(const float2*)&g_part[(c * BB + b) * DD + tid * 2];
            s.x += p.x;
            s.y += p.y;
        }
        sx[tid * 2]     = s.x;
        sx[tid * 2 + 1] = s.y;
    }
    __syncthreads();

    if (wid < CC) {
        float s = 0.f;
        #pragma unroll
        for (int it = 0; it < 10; ++it) {
            const int d = lane + it * 32;
            if (d < DD) s += sx[d] * wreg[it];
        }
        #pragma unroll
        for (int off = 16; off; off >>= 1)
            s += __shfl_down_sync(0xffffffffu, s, off);
        if (lane == 0)
            sh[wid] = fmaxf(s + bb, 0.f);
    }
    __syncthreads();

    if (wid == 0) {
        const float h = (lane < CC) ? sh[lane] : -1e30f;
        float m = h;
        #pragma unroll
        for (int off = 16; off; off >>= 1)
            m = fmaxf(m, __shfl_xor_sync(0xffffffffu, m, off));
        const float e = (lane < CC) ? expf(h - m) : 0.f;
        float sum = e;
        #pragma unroll
        for (int off = 16; off; off >>= 1)
            sum += __shfl_xor_sync(0xffffffffu, sum, off);
        if (lane < CC)
            out[b * CC + lane] = e / sum;
    }
}

extern "C" void kernel_launch(void* const* d_in, const int* in_sizes, int n_in,
                              void* d_out, int out_size)
{
    const int*   master = (const int*)  d_in[0];
    const int*   slave  = (const int*)  d_in[1];
    const int*   edge   = (const int*)  d_in[2];
    const float* R      = (const float*)d_in[3];
    const float* E      = (const float*)d_in[4];
    const float* Ngate  = (const float*)d_in[5];
    const float* W      = (const float*)d_in[6];
    const float* bias   = (const float*)d_in[7];
    float* out = (float*)d_out;

    cudaLaunchAttribute attr[1];
    attr[0].id = cudaLaunchAttributeProgrammaticStreamSerialization;
    attr[0].val.programmaticStreamSerializationAllowed = 1;

    // 1) prep: normal launch (gathers + convert only)
    prep_kernel<<<CVT_BLKS + EGATH_BLKS + NGATH_BLKS, 512>>>(R, master, edge,
                                                             E, Ngate);

    // 2) pool: PDL after prep
    {
        cudaLaunchConfig_t cfg = {};
        cfg.gridDim  = dim3(NCHUNK, BB);
        cfg.blockDim = dim3(160);
        cfg.stream   = 0;
        cfg.attrs    = attr;
        cfg.numAttrs = 1;
        cudaLaunchKernelEx(&cfg, gnn_pool_kernel, master, slave);
    }

    // 3) head: PDL after pool (W preload overlaps pool drain)
    {
        cudaLaunchConfig_t cfg = {};
        cfg.gridDim  = dim3(BB);
        cfg.blockDim = dim3(448);
        cfg.stream   = 0;
        cfg.attrs    = attr;
        cfg.numAttrs = 1;
        cudaLaunchKernelEx(&cfg, head_kernel, W, bias, out);
    }
}

// round 17
// speedup vs baseline: 1.3287x; 1.1787x over previous
#include <cuda_runtime.h>
#include <cuda_fp16.h>

#define BB 128
#define LL 512
#define KN 8
#define DD 300
#define CC 14
#define LCHUNK 32
#define NCHUNK (LL / LCHUNK)   // 16 -> 2048 pool blocks, 2 waves
#define NROWS 4905             // NUM_NODES + 1
#define RSTRIDE 320            // halves per row: 640B = 5 x 128B sectors
#define RH2 (RSTRIDE / 2)      // 160 half2 per row
#define CVT_WARPS 16
#define CVT_BLKS ((NROWS + CVT_WARPS - 1) / CVT_WARPS)   // 307

__device__ __half2 g_Rh2[NROWS * RH2];
__device__ float g_part[NCHUNK * BB * DD];

__device__ __forceinline__ void pdl_wait()
{
    asm volatile("griddepcontrol.wait;" ::: "memory");
}

// ---- convert: R -> fp16 padded rows (normal launch) ----
__global__ __launch_bounds__(512)
void convert_kernel(const float* __restrict__ R)
{
    const int wid  = threadIdx.x >> 5;
    const int lane = threadIdx.x & 31;
    const int row  = blockIdx.x * CVT_WARPS + wid;
    if (row >= NROWS) return;

    const float* src = R + row * DD;
    __half2*     dst = g_Rh2 + row * RH2;

    float2 v[5];
    #pragma unroll
    for (int j = 0; j < 5; ++j) {
        const int tt = lane + j * 32;
        v[j] = (tt < DD / 2) ? *(const float2*)&src[tt * 2]
                             : make_float2(0.f, 0.f);
    }
    #pragma unroll
    for (int j = 0; j < 5; ++j) {
        const int tt = lane + j * 32;
        if (tt < RH2)
            dst[tt] = __floats2half2_rn(v[j].x, v[j].y);
    }
}

// ---- pool: gathers in prologue (post-wait); 2 waves overlap gather/mainloop ----
__global__ __launch_bounds__(160)
void gnn_pool_kernel(const int*   __restrict__ master,
                     const int*   __restrict__ slave,
                     const int*   __restrict__ edge,
                     const float* __restrict__ E,
                     const float* __restrict__ Ngate)
{
    const int b     = blockIdx.y;
    const int chunk = blockIdx.x;
    const int tid   = threadIdx.x;

    // Wait FIRST: gathers must not run concurrently with convert (both
    // DRAM-bound -> additive, measured R9/R13/R14). Post-wait, wave-2
    // prologues overlap wave-1 mainloops instead.
    pdl_wait();

    __shared__ __align__(16) int   s_node[LCHUNK * KN];   // pre-scaled offsets
    __shared__ __align__(16) float s_e[LCHUNK * KN];
    __shared__ int   s_m[LCHUNK];
    __shared__ float s_g[LCHUNK];

    const int base = b * LL + chunk * LCHUNK;

    // MLP=4 gather prologue:
    //   threads 0..63 : one int4 slave + one int4 edge + 4 independent E gathers
    //   threads 64..95: one master + one Ngate gather
    if (tid < (LCHUNK * KN) / 4) {           // 64 int4 groups
        const int4 s4 = ((const int4*)slave)[base * 2 + tid];
        const int4 e4 = ((const int4*)edge)[base * 2 + tid];

        const float v0 = E[e4.x];
        const float v1 = E[e4.y];
        const float v2 = E[e4.z];
        const float v3 = E[e4.w];

        int4 n4;
        n4.x = s4.x * RH2;  n4.y = s4.y * RH2;
        n4.z = s4.z * RH2;  n4.w = s4.w * RH2;

        *(int4*)  &s_node[tid * 4] = n4;
        *(float4*)&s_e[tid * 4]    = make_float4(v0, v1, v2, v3);
    } else if (tid < (LCHUNK * KN) / 4 + LCHUNK) {
        const int p = tid - (LCHUNK * KN) / 4;
        const int m = master[base + p];
        s_m[p] = m * RH2;
        s_g[p] = Ngate[m];
    }
    __syncthreads();

    if (tid >= 150) return;   // 150 half2 lanes cover 300 dims

    const __half2* Rbase = g_Rh2 + tid;
    float2 acc = make_float2(0.f, 0.f);

    #pragma unroll 4
    for (int li = 0; li < LCHUNK; ++li) {
        const int4   n0 = *(const int4*)  &s_node[li * KN];
        const int4   n1 = *(const int4*)  &s_node[li * KN + 4];
        const float4 e0 = *(const float4*)&s_e[li * KN];
        const float4 e1 = *(const float4*)&s_e[li * KN + 4];

        const float2 f0 = __half22float2(Rbase[n0.x]);
        const float2 f1 = __half22float2(Rbase[n0.y]);
        const float2 f2 = __half22float2(Rbase[n0.z]);
        const float2 f3 = __half22float2(Rbase[n0.w]);
        const float2 f4 = __half22float2(Rbase[n1.x]);
        const float2 f5 = __half22float2(Rbase[n1.y]);
        const float2 f6 = __half22float2(Rbase[n1.z]);
        const float2 f7 = __half22float2(Rbase[n1.w]);
        const float2 fm = __half22float2(Rbase[s_m[li]]);

        float mx0 = f0.x * e0.x;
        float mx1 = f0.y * e0.x;
        mx0 = fmaxf(mx0, f1.x * e0.y);  mx1 = fmaxf(mx1, f1.y * e0.y);
        mx0 = fmaxf(mx0, f2.x * e0.z);  mx1 = fmaxf(mx1, f2.y * e0.z);
        mx0 = fmaxf(mx0, f3.x * e0.w);  mx1 = fmaxf(mx1, f3.y * e0.w);
        mx0 = fmaxf(mx0, f4.x * e1.x);  mx1 = fmaxf(mx1, f4.y * e1.x);
        mx0 = fmaxf(mx0, f5.x * e1.y);  mx1 = fmaxf(mx1, f5.y * e1.y);
        mx0 = fmaxf(mx0, f6.x * e1.z);  mx1 = fmaxf(mx1, f6.y * e1.z);
        mx0 = fmaxf(mx0, f7.x * e1.w);  mx1 = fmaxf(mx1, f7.y * e1.w);

        const float g = s_g[li];
        acc.x += mx0 + g * (fm.x - mx0);
        acc.y += mx1 + g * (fm.y - mx1);
    }

    float2* outp = (float2*)&g_part[(chunk * BB + b) * DD];
    outp[tid] = acc;
}

__global__ __launch_bounds__(448)
void head_kernel(const float* __restrict__ W,
                 const float* __restrict__ bias,
                 float* __restrict__ out)
{
    const int b    = blockIdx.x;
    const int tid  = threadIdx.x;
    const int wid  = tid >> 5;
    const int lane = tid & 31;

    __shared__ float sx[DD];
    __shared__ float sh[CC];

    // PRE-WAIT: W + bias loads (independent of pool)
    float wreg[10];
    float bb = 0.f;
    if (wid < CC) {
        #pragma unroll
        for (int it = 0; it < 10; ++it) {
            const int d = lane + it * 32;
            wreg[it] = (d < DD) ? W[wid * DD + d] : 0.f;
        }
        bb = bias[wid];
    }

    pdl_wait();   // g_part complete

    if (tid < 150) {
        float2 s = make_float2(0.f, 0.f);
        #pragma unroll
        for (int c = 0; c < NCHUNK; ++c) {
            const float2 p = *(const float2*)&g_part[(c * BB + b) * DD + tid * 2];
            s.x += p.x;
            s.y += p.y;
        }
        sx[tid * 2]     = s.x;
        sx[tid * 2 + 1] = s.y;
    }
    __syncthreads();

    if (wid < CC) {
        float s = 0.f;
        #pragma unroll
        for (int it = 0; it < 10; ++it) {
            const int d = lane + it * 32;
            if (d < DD) s += sx[d] * wreg[it];
        }
        #pragma unroll
        for (int off = 16; off; off >>= 1)
            s += __shfl_down_sync(0xffffffffu, s, off);
        if (lane == 0)
            sh[wid] = fmaxf(s + bb, 0.f);
    }
    __syncthreads();

    if (wid == 0) {
        const float h = (lane < CC) ? sh[lane] : -1e30f;
        float m = h;
        #pragma unroll
        for (int off = 16; off; off >>= 1)
            m = fmaxf(m, __shfl_xor_sync(0xffffffffu, m, off));
        const float e = (lane < CC) ? expf(h - m) : 0.f;
        float sum = e;
        #pragma unroll
        for (int off = 16; off; off >>= 1)
            sum += __shfl_xor_sync(0xffffffffu, sum, off);
        if (lane < CC)
            out[b * CC + lane] = e / sum;
    }
}

extern "C" void kernel_launch(void* const* d_in, const int* in_sizes, int n_in,
                              void* d_out, int out_size)
{
    const int*   master = (const int*)  d_in[0];
    const int*   slave  = (const int*)  d_in[1];
    const int*   edge   = (const int*)  d_in[2];
    const float* R      = (const float*)d_in[3];
    const float* E      = (const float*)d_in[4];
    const float* Ngate  = (const float*)d_in[5];
    const float* W      = (const float*)d_in[6];
    const float* bias   = (const float*)d_in[7];
    float* out = (float*)d_out;

    cudaLaunchAttribute attr[1];
    attr[0].id = cudaLaunchAttributeProgrammaticStreamSerialization;
    attr[0].val.programmaticStreamSerializationAllowed = 1;

    // 1) convert: normal launch (DRAM-streaming, runs alone)
    convert_kernel<<<CVT_BLKS, 512>>>(R);

    // 2) pool: PDL — post-wait prologue gathers; 2 waves overlap gather/compute
    {
        cudaLaunchConfig_t cfg = {};
        cfg.gridDim  = dim3(NCHUNK, BB);
        cfg.blockDim = dim3(160);
        cfg.stream   = 0;
        cfg.attrs    = attr;
        cfg.numAttrs = 1;
        cudaLaunchKernelEx(&cfg, gnn_pool_kernel, master, slave, edge, E, Ngate);
    }

    // 3) head: PDL — W preload overlaps pool drain
    {
        cudaLaunchConfig_t cfg = {};
        cfg.gridDim  = dim3(BB);
        cfg.blockDim = dim3(448);
        cfg.stream   = 0;
        cfg.attrs    = attr;
        cfg.numAttrs = 1;
        cudaLaunchKernelEx(&cfg, head_kernel, W, bias, out);
    }
}